// round 17
// baseline (speedup 1.0000x reference)
#include <cuda_runtime.h>
#include <cuda_bf16.h>
#include <cstdint>

// Shapes: T=64, B=512, D=768, H=12, HD=64
#define T_DIM 64
#define B_DIM 512
#define D_DIM 768
#define H_DIM 12
#define HD_DIM 64
#define ROWS (T_DIM * B_DIM)          // 32768
#define QKV_N (3 * D_DIM)             // 2304

typedef unsigned long long u64;
typedef __nv_bfloat16 bf16;

__device__ __forceinline__ uint32_t smem_to_u32(const void* p) {
    uint32_t a;
    asm("{ .reg .u64 t; cvta.to.shared.u64 t, %1; cvt.u32.u64 %0, t; }"
        : "=r"(a) : "l"(p));
    return a;
}

#define SWZ(x) ((x) ^ (((x) >> 3) & 0x70))

__device__ __forceinline__ void cp16(uint32_t dst, const void* src) {
    asm volatile("cp.async.cg.shared.global [%0], [%1], 16;"
                 :: "r"(dst), "l"(src));
}
__device__ __forceinline__ void cp_commit() {
    asm volatile("cp.async.commit_group;");
}
__device__ __forceinline__ void cp_wait0() {
    asm volatile("cp.async.wait_group 0;");
}
__device__ __forceinline__ void cp_wait1() {
    asm volatile("cp.async.wait_group 1;");
}

__device__ __forceinline__ void ldmx4(uint32_t* r, uint32_t addr) {
    asm volatile("ldmatrix.sync.aligned.m8n8.x4.shared.b16 {%0,%1,%2,%3}, [%4];"
                 : "=r"(r[0]), "=r"(r[1]), "=r"(r[2]), "=r"(r[3]) : "r"(addr));
}
__device__ __forceinline__ void ldmx4t(uint32_t* r, uint32_t addr) {
    asm volatile("ldmatrix.sync.aligned.m8n8.x4.trans.shared.b16 {%0,%1,%2,%3}, [%4];"
                 : "=r"(r[0]), "=r"(r[1]), "=r"(r[2]), "=r"(r[3]) : "r"(addr));
}
__device__ __forceinline__ void mma16816(float* d, const uint32_t* a,
                                         uint32_t b0, uint32_t b1) {
    asm volatile(
        "mma.sync.aligned.m16n8k16.row.col.f32.bf16.bf16.f32 "
        "{%0,%1,%2,%3}, {%4,%5,%6,%7}, {%8,%9}, {%0,%1,%2,%3};"
        : "+f"(d[0]), "+f"(d[1]), "+f"(d[2]), "+f"(d[3])
        : "r"(a[0]), "r"(a[1]), "r"(a[2]), "r"(a[3]), "r"(b0), "r"(b1));
}

__device__ __forceinline__ float fast_ex2(float x) {
    float r;
    asm("ex2.approx.ftz.f32 %0, %1;" : "=f"(r) : "f"(x));
    return r;
}
__device__ __forceinline__ void hilo_pack(float x, float y, uint32_t& hw, uint32_t& lw) {
    union { bf16 b[2]; uint32_t u; } H, L;
    H.b[0] = __float2bfloat16_rn(x);
    H.b[1] = __float2bfloat16_rn(y);
    L.b[0] = __float2bfloat16_rn(x - __bfloat162float(H.b[0]));
    L.b[1] = __float2bfloat16_rn(y - __bfloat162float(H.b[1]));
    hw = H.u; lw = L.u;
}

// ---------------- scratch (device globals; no allocations) ----------------
__device__ float g_out[(size_t)ROWS * D_DIM];
__device__ float g_invn[ROWS];
__device__ float g_svec[T_DIM * D_DIM];
__device__ __align__(16) bf16 g_qkvh[(size_t)ROWS * QKV_N];
__device__ __align__(16) bf16 g_qkvl[(size_t)ROWS * QKV_N];
__device__ __align__(16) bf16 g_xh[(size_t)ROWS * D_DIM];
__device__ __align__(16) bf16 g_xl[(size_t)ROWS * D_DIM];
__device__ __align__(16) bf16 g_ch[(size_t)ROWS * D_DIM];
__device__ __align__(16) bf16 g_cl[(size_t)ROWS * D_DIM];
__device__ __align__(16) bf16 g_w1h[(size_t)QKV_N * D_DIM];
__device__ __align__(16) bf16 g_w1l[(size_t)QKV_N * D_DIM];
__device__ __align__(16) bf16 g_w2h[(size_t)D_DIM * D_DIM];
__device__ __align__(16) bf16 g_w2l[(size_t)D_DIM * D_DIM];

// ---------------- fp32 -> bf16 hi/lo split ----------------
__global__ __launch_bounds__(256)
void cvt_hilo(const float* __restrict__ x, bf16* __restrict__ h,
              bf16* __restrict__ l, int n4)
{
    int i = blockIdx.x * 256 + threadIdx.x;
    if (i >= n4) return;
    float4 v = ((const float4*)x)[i];
    union { bf16 b[4]; uint2 u; } ph, pl;
    ph.b[0] = __float2bfloat16_rn(v.x);
    ph.b[1] = __float2bfloat16_rn(v.y);
    ph.b[2] = __float2bfloat16_rn(v.z);
    ph.b[3] = __float2bfloat16_rn(v.w);
    pl.b[0] = __float2bfloat16_rn(v.x - __bfloat162float(ph.b[0]));
    pl.b[1] = __float2bfloat16_rn(v.y - __bfloat162float(ph.b[1]));
    pl.b[2] = __float2bfloat16_rn(v.z - __bfloat162float(ph.b[2]));
    pl.b[3] = __float2bfloat16_rn(v.w - __bfloat162float(ph.b[3]));
    ((uint2*)h)[i] = ph.u;
    ((uint2*)l)[i] = pl.u;
}

// ------------- mma.sync bf16 GEMM-NT: C = A*B^T + bias, 3x-split ----------
// Virtual K = 3*K via segments (Ah,Bh), (Ah,Bl), (Al,Bh).
// CTA tile 128x256, BK=64, 256 threads (8 warps, 2x4), warp tile 64x64.
// 3-stage cp.async pipeline: stage = A(16KB) + B(32KB) = 48KB, x3 = 144KB.
// Epilogue staging reuses smem as 128 x 260 f32 (133KB).
#define GEMM_SMEM_BYTES (3 * 49152)

__global__ __launch_bounds__(256, 1)
void gemm_tc(const bf16* __restrict__ Agh, const bf16* __restrict__ Agl,
             const bf16* __restrict__ Bgh, const bf16* __restrict__ Bgl,
             const float* __restrict__ bias, float* __restrict__ C,
             bf16* __restrict__ Chi, bf16* __restrict__ Clo,
             int N, int K)
{
    extern __shared__ __align__(1024) char smem[];
    const uint32_t sb = smem_to_u32(smem);
    const int tid = threadIdx.x;
    const int wid = tid >> 5, lane = tid & 31;
    const int wm = wid >> 2, wn = wid & 3;       // 2 x 4 warp grid
    const int m0 = blockIdx.y * 128, n0 = blockIdx.x * 256;

    const int NSEG_T = K / 64;
    const int NT = 3 * NSEG_T;

    float d[4][8][4];
#pragma unroll
    for (int i = 0; i < 4; i++)
#pragma unroll
        for (int j = 0; j < 8; j++)
#pragma unroll
            for (int k = 0; k < 4; k++) d[i][j][k] = 0.f;

    const int lrow = tid >> 3, lch = tid & 7;    // 8 threads per 128B row

    auto load_tile = [&](int it, int b) {
        int seg = it / NSEG_T;
        long koff = (long)(it - seg * NSEG_T) * 64;
        const bf16* As_ = (seg < 2) ? Agh : Agl;
        const bf16* Bs_ = (seg == 1) ? Bgl : Bgh;
        uint32_t tA = sb + b * 49152;
        uint32_t tB = tA + 16384;
#pragma unroll
        for (int p = 0; p < 4; p++) {            // A: 128 rows
            int row = lrow + p * 32;
            uint32_t off = SWZ((uint32_t)(row * 128 + lch * 16));
            cp16(tA + off, As_ + (long)(m0 + row) * K + koff + lch * 8);
        }
#pragma unroll
        for (int p = 0; p < 8; p++) {            // B: 256 rows
            int row = lrow + p * 32;
            uint32_t off = SWZ((uint32_t)(row * 128 + lch * 16));
            cp16(tB + off, Bs_ + (long)(n0 + row) * K + koff + lch * 8);
        }
        cp_commit();
    };

    load_tile(0, 0);
    load_tile(1, 1);

    int buf = 0;
    for (int it = 0; it < NT; ++it) {
        if (it + 2 < NT) cp_wait1(); else cp_wait0();
        __syncthreads();
        // 3 buffers: (it+2)%3 is neither read now nor in flight; barrier above
        // retired all reads of it from iteration it-1.
        if (it + 2 < NT) load_tile(it + 2, (it + 2) % 3);

        uint32_t tA = sb + buf * 49152;
        uint32_t tB = tA + 16384;

#pragma unroll
        for (int ks = 0; ks < 4; ks++) {
            uint32_t a[4][4];
#pragma unroll
            for (int mi = 0; mi < 4; mi++) {
                int row = wm * 64 + mi * 16 + (lane & 15);
                uint32_t off = (uint32_t)(row * 128 + (2 * ks + (lane >> 4)) * 16);
                ldmx4(a[mi], tA + SWZ(off));
            }
#pragma unroll
            for (int nb = 0; nb < 4; nb++) {
                uint32_t b4[4];
                int row = wn * 64 + nb * 16 + (lane & 7) + ((lane >> 4) << 3);
                uint32_t off = (uint32_t)(row * 128 + (2 * ks + ((lane >> 3) & 1)) * 16);
                ldmx4(b4, tB + SWZ(off));
#pragma unroll
                for (int mi = 0; mi < 4; mi++) {
                    mma16816(d[mi][2 * nb],     a[mi], b4[0], b4[1]);
                    mma16816(d[mi][2 * nb + 1], a[mi], b4[2], b4[3]);
                }
            }
        }
        buf = (buf + 1 == 3) ? 0 : buf + 1;
    }
    __syncthreads();

    // ---- epilogue: stage to smem (128 x 260 f32), coalesced stores + bias ----
    float* sf = (float*)smem;
#pragma unroll
    for (int mi = 0; mi < 4; mi++)
#pragma unroll
        for (int ni = 0; ni < 8; ni++) {
            int row = wm * 64 + mi * 16 + (lane >> 2);
            int col = wn * 64 + ni * 8 + 2 * (lane & 3);
            *(float2*)&sf[row * 260 + col]       = make_float2(d[mi][ni][0], d[mi][ni][1]);
            *(float2*)&sf[(row + 8) * 260 + col] = make_float2(d[mi][ni][2], d[mi][ni][3]);
        }
    __syncthreads();
#pragma unroll
    for (int p = 0; p < 32; p++) {
        int lin = p * 256 + tid;
        int row = lin >> 6, q = (lin & 63) * 4;
        const float* sr = sf + row * 260 + q;
        int n = n0 + q;
        float4 o;
        o.x = sr[0] + bias[n + 0];
        o.y = sr[1] + bias[n + 1];
        o.z = sr[2] + bias[n + 2];
        o.w = sr[3] + bias[n + 3];
        long idx = (long)(m0 + row) * N + n;
        if (Chi) {
            union { bf16 b[4]; uint2 u; } hh, ll;
            hh.b[0] = __float2bfloat16_rn(o.x);
            hh.b[1] = __float2bfloat16_rn(o.y);
            hh.b[2] = __float2bfloat16_rn(o.z);
            hh.b[3] = __float2bfloat16_rn(o.w);
            ll.b[0] = __float2bfloat16_rn(o.x - __bfloat162float(hh.b[0]));
            ll.b[1] = __float2bfloat16_rn(o.y - __bfloat162float(hh.b[1]));
            ll.b[2] = __float2bfloat16_rn(o.z - __bfloat162float(hh.b[2]));
            ll.b[3] = __float2bfloat16_rn(o.w - __bfloat162float(hh.b[3]));
            *(uint2*)(Chi + idx) = hh.u;
            *(uint2*)(Clo + idx) = ll.u;
        } else {
            *(float4*)(C + idx) = o;
        }
    }
}

// ---------------- tensor-core attention over B axis, 3x-split ------------
// CTA: (qb, h, t); 256 thr / 8 warps, each warp m16 query rows.
// KV processed in 8 blocks of 64 rows, DOUBLE-BUFFERED cp.async.
// SMEM: Qh|Ql (128x64, 32KB) + 2 x [Kh|Kl|Vh|Vl](64x64 each, 32KB) = 96KB.
#define ATTN_SMEM_BYTES (98304)

__global__ __launch_bounds__(256, 2)
void attn_tc(const bf16* __restrict__ qh, const bf16* __restrict__ ql,
             bf16* __restrict__ ctxh, bf16* __restrict__ ctxl)
{
    extern __shared__ __align__(1024) char smem[];
    const uint32_t sb = smem_to_u32(smem);
    const uint32_t sQh = sb, sQl = sb + 16384;

    const int qb = blockIdx.x, h = blockIdx.y, t = blockIdx.z;
    const int tid = threadIdx.x;
    const int w = tid >> 5, lane = tid & 31;
    const long rs = QKV_N;
    const bf16* bh = qh + (long)t * B_DIM * rs + h * HD_DIM;
    const bf16* bl = ql + (long)t * B_DIM * rs + h * HD_DIM;

    // Q loader: 2 threads per 128B row
    {
        const int lrow = tid >> 1, lc0 = (tid & 1) * 4;
        const bf16* srcH = bh + (long)(qb * 128 + lrow) * rs;
        const bf16* srcL = bl + (long)(qb * 128 + lrow) * rs;
#pragma unroll
        for (int c = 0; c < 4; c++) {
            uint32_t off = SWZ((uint32_t)(lrow * 128 + (lc0 + c) * 16));
            cp16(sQh + off, srcH + (lc0 + c) * 8);
            cp16(sQl + off, srcL + (lc0 + c) * 8);
        }
    }
    // KV loader: 64-row block into buffer bb; 4 threads per row, 2 chunks each
    const int krow = tid >> 2, kc0 = (tid & 3) * 2;
    auto load_kv = [&](int blk, int bb) {
        uint32_t base = sb + 32768 + bb * 32768;
        const bf16* kH = bh + D_DIM + (long)(blk * 64 + krow) * rs;
        const bf16* kL = bl + D_DIM + (long)(blk * 64 + krow) * rs;
        const bf16* vH = bh + 2 * D_DIM + (long)(blk * 64 + krow) * rs;
        const bf16* vL = bl + 2 * D_DIM + (long)(blk * 64 + krow) * rs;
#pragma unroll
        for (int c = 0; c < 2; c++) {
            uint32_t off = SWZ((uint32_t)(krow * 128 + (kc0 + c) * 16));
            cp16(base + off,         kH + (kc0 + c) * 8);
            cp16(base + 8192 + off,  kL + (kc0 + c) * 8);
            cp16(base + 16384 + off, vH + (kc0 + c) * 8);
            cp16(base + 24576 + off, vL + (kc0 + c) * 8);
        }
        cp_commit();
    };

    load_kv(0, 0);   // group0 = Q + KV0
    load_kv(1, 1);

    float ctx[8][4];
#pragma unroll
    for (int f = 0; f < 8; f++)
#pragma unroll
        for (int e = 0; e < 4; e++) ctx[f][e] = 0.f;
    float esum0 = 0.f, esum1 = 0.f;
    const float SCL = 0.125f * 1.44269504f;   // log2(e)/sqrt(64)

    for (int blk = 0; blk < 8; blk++) {
        if (blk + 2 < 8) cp_wait1(); else cp_wait0();
        __syncthreads();
        const uint32_t base = sb + 32768 + (blk & 1) * 32768;
        const uint32_t sKh = base, sKl = base + 8192;
        const uint32_t sVh = base + 16384, sVl = base + 24576;

        float s[8][4];
#pragma unroll
        for (int f = 0; f < 8; f++)
#pragma unroll
            for (int e = 0; e < 4; e++) s[f][e] = 0.f;

        // ---- S = Q K^T (3 splits), m16 x n64 ----
#pragma unroll
        for (int ks = 0; ks < 4; ks++) {
            uint32_t Ah[4], Al[4];
            {
                int arow = w * 16 + (lane & 15);
                uint32_t off = SWZ((uint32_t)(arow * 128 + (2 * ks + (lane >> 4)) * 16));
                ldmx4(Ah, sQh + off);
                ldmx4(Al, sQl + off);
            }
#pragma unroll
            for (int nj = 0; nj < 4; nj++) {
                int brow = nj * 16 + (lane & 7) + ((lane >> 4) << 3);
                uint32_t off = SWZ((uint32_t)(brow * 128 + (2 * ks + ((lane >> 3) & 1)) * 16));
                uint32_t Bh[4], Bl[4];
                ldmx4(Bh, sKh + off);
                ldmx4(Bl, sKl + off);
                mma16816(s[2 * nj],     Ah, Bh[0], Bh[1]);
                mma16816(s[2 * nj + 1], Ah, Bh[2], Bh[3]);
                mma16816(s[2 * nj],     Ah, Bl[0], Bl[1]);
                mma16816(s[2 * nj + 1], Ah, Bl[2], Bl[3]);
                mma16816(s[2 * nj],     Al, Bh[0], Bh[1]);
                mma16816(s[2 * nj + 1], Al, Bh[2], Bh[3]);
            }
        }

        // ---- exp + row-sum ----
#pragma unroll
        for (int f = 0; f < 8; f++) {
            s[f][0] = fast_ex2(s[f][0] * SCL);
            s[f][1] = fast_ex2(s[f][1] * SCL);
            s[f][2] = fast_ex2(s[f][2] * SCL);
            s[f][3] = fast_ex2(s[f][3] * SCL);
            esum0 += s[f][0] + s[f][1];
            esum1 += s[f][2] + s[f][3];
        }

        // ---- ctx += P V (3 splits) ----
#pragma unroll
        for (int ks = 0; ks < 4; ks++) {
            uint32_t Ph[4], Pl[4];
            hilo_pack(s[2 * ks][0],     s[2 * ks][1],     Ph[0], Pl[0]);
            hilo_pack(s[2 * ks][2],     s[2 * ks][3],     Ph[1], Pl[1]);
            hilo_pack(s[2 * ks + 1][0], s[2 * ks + 1][1], Ph[2], Pl[2]);
            hilo_pack(s[2 * ks + 1][2], s[2 * ks + 1][3], Ph[3], Pl[3]);
#pragma unroll
            for (int n0 = 0; n0 < 4; n0++) {
                int vrow = ks * 16 + (lane & 7) + (((lane >> 3) & 1) << 3);
                uint32_t off = SWZ((uint32_t)(vrow * 128 + (n0 * 16 + (lane >> 4) * 8) * 2));
                uint32_t Vh_[4], Vl_[4];
                ldmx4t(Vh_, sVh + off);
                ldmx4t(Vl_, sVl + off);
                mma16816(ctx[2 * n0],     Ph, Vh_[0], Vh_[1]);
                mma16816(ctx[2 * n0 + 1], Ph, Vh_[2], Vh_[3]);
                mma16816(ctx[2 * n0],     Ph, Vl_[0], Vl_[1]);
                mma16816(ctx[2 * n0 + 1], Ph, Vl_[2], Vl_[3]);
                mma16816(ctx[2 * n0],     Pl, Vh_[0], Vh_[1]);
                mma16816(ctx[2 * n0 + 1], Pl, Vh_[2], Vh_[3]);
            }
        }

        __syncthreads();   // all reads of buffer blk&1 retired before refill
        if (blk + 2 < 8) load_kv(blk + 2, blk & 1);
    }

    // ---- normalize + write ctx hi/lo ----
    esum0 += __shfl_xor_sync(0xffffffffu, esum0, 1);
    esum0 += __shfl_xor_sync(0xffffffffu, esum0, 2);
    esum1 += __shfl_xor_sync(0xffffffffu, esum1, 1);
    esum1 += __shfl_xor_sync(0xffffffffu, esum1, 2);
    float inv0 = 1.f / esum0, inv1 = 1.f / esum1;

    long row0 = ((long)t * B_DIM + qb * 128 + w * 16 + (lane >> 2)) * D_DIM + h * HD_DIM;
    long row1 = row0 + 8 * D_DIM;
#pragma unroll
    for (int f = 0; f < 8; f++) {
        int col = f * 8 + 2 * (lane & 3);
        uint32_t hw, lw;
        hilo_pack(ctx[f][0] * inv0, ctx[f][1] * inv0, hw, lw);
        *(uint32_t*)(ctxh + row0 + col) = hw;
        *(uint32_t*)(ctxl + row0 + col) = lw;
        hilo_pack(ctx[f][2] * inv1, ctx[f][3] * inv1, hw, lw);
        *(uint32_t*)(ctxh + row1 + col) = hw;
        *(uint32_t*)(ctxl + row1 + col) = lw;
    }
}

// ---------------- epilogue kernels ----------------
__global__ __launch_bounds__(256)
void rownorm_kernel(const float* __restrict__ o, float* __restrict__ invn)
{
    int row = blockIdx.x * 8 + (threadIdx.x >> 5);
    int lane = threadIdx.x & 31;
    const float* p = o + (long)row * D_DIM;
    float ss = 0.f;
#pragma unroll
    for (int k = 0; k < 6; k++) {
        float4 v = *(const float4*)(p + lane * 4 + k * 128);
        ss += v.x * v.x + v.y * v.y + v.z * v.z + v.w * v.w;
    }
#pragma unroll
    for (int off = 16; off; off >>= 1) ss += __shfl_xor_sync(0xffffffffu, ss, off);
    if (lane == 0) invn[row] = 1.f / fmaxf(sqrtf(ss), 1e-8f);
}

__global__ __launch_bounds__(256)
void meanvec_kernel(const float* __restrict__ o, const float* __restrict__ invn,
                    float* __restrict__ svec)
{
    int t = blockIdx.y;
    int d = blockIdx.x * 256 + threadIdx.x;
    const float* p = o + (long)t * B_DIM * D_DIM + d;
    const float* iv = invn + t * B_DIM;
    float s = 0.f;
#pragma unroll 8
    for (int b = 0; b < B_DIM; b++) s += p[(long)b * D_DIM] * iv[b];
    svec[t * D_DIM + d] = s;
}

__global__ __launch_bounds__(256)
void adj_kernel(const float* __restrict__ o, const float* __restrict__ invn,
                const float* __restrict__ svec, float* __restrict__ adj)
{
    int row = blockIdx.x * 8 + (threadIdx.x >> 5);
    int lane = threadIdx.x & 31;
    int t = row >> 9;
    const float* p = o + (long)row * D_DIM;
    const float* sv = svec + t * D_DIM;
    float acc = 0.f;
#pragma unroll
    for (int k = 0; k < 6; k++) {
        float4 v = *(const float4*)(p + lane * 4 + k * 128);
        float4 s = *(const float4*)(sv + lane * 4 + k * 128);
        acc += v.x * s.x + v.y * s.y + v.z * s.z + v.w * s.w;
    }
#pragma unroll
    for (int off = 16; off; off >>= 1) acc += __shfl_xor_sync(0xffffffffu, acc, off);
    if (lane == 0) adj[row] = acc * invn[row] * (1.0f / (float)B_DIM);
}

// ---------------- launch ----------------
extern "C" void kernel_launch(void* const* d_in, const int* in_sizes, int n_in,
                              void* d_out, int out_size)
{
    const float* x  = (const float*)d_in[0];   // node_embs (T,B,D)
    const float* w1 = (const float*)d_in[1];   // in_proj_w (3D,D)
    const float* b1 = (const float*)d_in[2];   // in_proj_b (3D)
    const float* w2 = (const float*)d_in[3];   // out_proj_w (D,D)
    const float* b2 = (const float*)d_in[4];   // out_proj_b (D)
    float* adj = (float*)d_out;                // (T,B,1)

    float *outb, *invn, *svec;
    bf16 *qkvh, *qkvl, *xh, *xl, *chh, *cl, *w1h, *w1l, *w2h, *w2l;
    cudaGetSymbolAddress((void**)&outb, g_out);
    cudaGetSymbolAddress((void**)&invn, g_invn);
    cudaGetSymbolAddress((void**)&svec, g_svec);
    cudaGetSymbolAddress((void**)&qkvh, g_qkvh);
    cudaGetSymbolAddress((void**)&qkvl, g_qkvl);
    cudaGetSymbolAddress((void**)&xh,  g_xh);
    cudaGetSymbolAddress((void**)&xl,  g_xl);
    cudaGetSymbolAddress((void**)&chh, g_ch);
    cudaGetSymbolAddress((void**)&cl,  g_cl);
    cudaGetSymbolAddress((void**)&w1h, g_w1h);
    cudaGetSymbolAddress((void**)&w1l, g_w1l);
    cudaGetSymbolAddress((void**)&w2h, g_w2h);
    cudaGetSymbolAddress((void**)&w2l, g_w2l);

    cudaFuncSetAttribute(gemm_tc, cudaFuncAttributeMaxDynamicSharedMemorySize,
                         GEMM_SMEM_BYTES);
    cudaFuncSetAttribute(attn_tc, cudaFuncAttributeMaxDynamicSharedMemorySize,
                         ATTN_SMEM_BYTES);

    // 0) bf16 hi/lo splits of x, w1, w2
    {
        int n4 = ROWS * D_DIM / 4;
        cvt_hilo<<<(n4 + 255) / 256, 256>>>(x, xh, xl, n4);
    }
    {
        int n4 = QKV_N * D_DIM / 4;
        cvt_hilo<<<(n4 + 255) / 256, 256>>>(w1, w1h, w1l, n4);
    }
    {
        int n4 = D_DIM * D_DIM / 4;
        cvt_hilo<<<(n4 + 255) / 256, 256>>>(w2, w2h, w2l, n4);
    }

    // 1) qkv = x @ W1^T + b1  -> bf16 hi/lo directly  (N tiles of 256)
    gemm_tc<<<dim3(QKV_N / 256, ROWS / 128), 256, GEMM_SMEM_BYTES>>>(
        xh, xl, w1h, w1l, b1, nullptr, qkvh, qkvl, QKV_N, D_DIM);

    // 2) tensor-core attention (double-buffered KV) -> ctx hi/lo directly
    attn_tc<<<dim3(B_DIM / 128, H_DIM, T_DIM), 256, ATTN_SMEM_BYTES>>>(
        qkvh, qkvl, chh, cl);

    // 3) out = ctx @ W2^T + b2 (fp32 out)
    gemm_tc<<<dim3(D_DIM / 256, ROWS / 128), 256, GEMM_SMEM_BYTES>>>(
        chh, cl, w2h, w2l, b2, outb, nullptr, nullptr, D_DIM, D_DIM);

    // 4-6) cosine-sim epilogue (collapsed via mean-vector identity)
    rownorm_kernel<<<ROWS / 8, 256>>>(outb, invn);
    meanvec_kernel<<<dim3(D_DIM / 256, T_DIM), 256>>>(outb, invn, svec);
    adj_kernel<<<ROWS / 8, 256>>>(outb, invn, svec, adj);
}